// round 5
// baseline (speedup 1.0000x reference)
#include <cuda_runtime.h>
#include <cuda_bf16.h>

#define NN 50000
#define EE 800000
#define FD 128           // hidden = heads*C = 2*64
#define NEG 0.2f
#define BN_EPS 1e-5f

// ---------------- scratch (device globals; referenced ONLY inside kernels) ----
__device__ __align__(16) float  g_h[NN * FD];    // GEMM output (per-layer features)
__device__ __align__(16) float  g_agg[NN * FD];  // GAT aggregate output (pre-BN)
__device__ __align__(16) float  g_x2[NN * FD];   // layer-2 input (post BN+ELU of L1)
__device__ float2 g_asrc[NN];          // per-node attention src scores (2 heads)
__device__ float2 g_adst[NN];          // per-node attention dst scores (2 heads)
__device__ float2 g_ex[EE];            // per-edge logits -> exp values (2 heads)
__device__ int    g_counts[NN];
__device__ int    g_cursor[NN];
__device__ int    g_offsets[NN + 1];
__device__ int    g_srt[EE];           // src node ids, sorted by dst (CSR)
__device__ double g_bnsum[FD];
__device__ double g_bnsq[FD];

__device__ __forceinline__ int clampN(int v) {
    return v < 0 ? 0 : (v >= NN ? NN - 1 : v);
}

// ---------------- counting sort by destination ----------------
__global__ void k_zero_counts() {
    int i = blockIdx.x * blockDim.x + threadIdx.x;
    if (i < NN) g_counts[i] = 0;
}

__global__ void k_hist(const int* __restrict__ dst) {
    int e = blockIdx.x * blockDim.x + threadIdx.x;
    if (e < EE) atomicAdd(&g_counts[clampN(dst[e])], 1);
}

// single-block scan: 1024 threads, each owns a contiguous chunk
__global__ void k_scan() {
    __shared__ int ssum[1024];
    const int CH = (NN + 1023) / 1024;   // 49
    int t = threadIdx.x;
    int base = t * CH;
    int s = 0;
    for (int i = 0; i < CH; i++) {
        int idx = base + i;
        if (idx < NN) s += g_counts[idx];
    }
    ssum[t] = s;
    __syncthreads();
    for (int o = 1; o < 1024; o <<= 1) {
        int u = (t >= o) ? ssum[t - o] : 0;
        __syncthreads();
        ssum[t] += u;
        __syncthreads();
    }
    int off = ssum[t] - s;   // exclusive prefix of this thread's chunk
    for (int i = 0; i < CH; i++) {
        int idx = base + i;
        if (idx < NN) {
            g_offsets[idx] = off;
            g_cursor[idx]  = off;
            off += g_counts[idx];
        }
    }
    if (t == 0) g_offsets[NN] = EE;
}

__global__ void k_scatter(const int* __restrict__ src,
                          const int* __restrict__ dst) {
    int e = blockIdx.x * blockDim.x + threadIdx.x;
    if (e < EE) {
        int d = clampN(dst[e]);
        int p = atomicAdd(&g_cursor[d], 1);
        if (p >= 0 && p < EE) g_srt[p] = clampN(src[e]);
    }
}

// ---------------- GEMM: g_h = Xin @ W, Xin:[NN,128], W:[128,128] ----------------
// static smem: X tile 32x128 (16KB) + W chunk 64x128 (32KB) = 48KB
__global__ void k_gemm(const float* __restrict__ X, const float* __restrict__ W,
                       int use_x2) {
    __shared__ float Ws[64 * FD];   // 32 KB
    __shared__ float Xs[32 * FD];   // 16 KB
    int t = threadIdx.x;
    int rb = blockIdx.x * 32;
    const float* Xp = use_x2 ? g_x2 : X;

    // load X tile (1024 float4)
    float4* Xs4 = (float4*)Xs;
    const float4* X4 = (const float4*)Xp;
    for (int i = t; i < 32 * FD / 4; i += 256) {
        int r = i >> 5;          // 32 float4 per row
        int c = i & 31;
        int gr = rb + r;
        Xs4[i] = (gr < NN) ? X4[gr * 32 + c] : make_float4(0.f, 0.f, 0.f, 0.f);
    }

    int lane = t & 31;
    int warp = t >> 5;           // 8 warps -> rows warp, warp+8, +16, +24
    float4 acc[4] = {{0,0,0,0},{0,0,0,0},{0,0,0,0},{0,0,0,0}};
    float4* Ws4 = (float4*)Ws;

    #pragma unroll
    for (int chunk = 0; chunk < 2; chunk++) {
        __syncthreads();   // X tile ready (iter 0) / prior-chunk compute done (iter 1)
        const float4* W4 = (const float4*)(W + chunk * 64 * FD);
        for (int i = t; i < 64 * FD / 4; i += 256) Ws4[i] = W4[i];
        __syncthreads();

        #pragma unroll 4
        for (int k = 0; k < 64; k++) {
            float4 wv = *(const float4*)&Ws[k * FD + lane * 4];
            #pragma unroll
            for (int i = 0; i < 4; i++) {
                float xv = Xs[(warp + i * 8) * FD + chunk * 64 + k];
                acc[i].x += xv * wv.x;
                acc[i].y += xv * wv.y;
                acc[i].z += xv * wv.z;
                acc[i].w += xv * wv.w;
            }
        }
    }
    #pragma unroll
    for (int i = 0; i < 4; i++) {
        int r = rb + warp + i * 8;
        if (r < NN) ((float4*)g_h)[r * 32 + lane] = acc[i];
    }
}

// ---------------- per-node attention scores (reads g_h) ----------------
__global__ void k_att(const float* __restrict__ att_s,
                      const float* __restrict__ att_d) {
    int w = (blockIdx.x * blockDim.x + threadIdx.x) >> 5;
    int lane = threadIdx.x & 31;
    if (w >= NN) return;
    float4 hv  = ((const float4*)g_h)[w * 32 + lane];
    float4 as  = ((const float4*)att_s)[lane];  // [2,64] flat == channel order
    float4 ad  = ((const float4*)att_d)[lane];
    float ds = hv.x * as.x + hv.y * as.y + hv.z * as.z + hv.w * as.w;
    float dd = hv.x * ad.x + hv.y * ad.y + hv.z * ad.z + hv.w * ad.w;
    #pragma unroll
    for (int o = 8; o; o >>= 1) {    // reduce within 16-lane head groups
        ds += __shfl_xor_sync(0xFFFFFFFFu, ds, o);
        dd += __shfl_xor_sync(0xFFFFFFFFu, dd, o);
    }
    if (lane == 0)  { g_asrc[w].x = ds; g_adst[w].x = dd; }
    if (lane == 16) { g_asrc[w].y = ds; g_adst[w].y = dd; }
}

// ---------------- warp-per-dst aggregation (softmax + weighted sum) ----------------
__global__ void k_agg(const float* __restrict__ bias) {
    int w = (blockIdx.x * blockDim.x + threadIdx.x) >> 5;
    int lane = threadIdx.x & 31;
    if (w >= NN) return;
    int start = g_offsets[w];
    int deg   = g_offsets[w + 1] - start;

    float2 ad  = g_adst[w];
    float2 asf = g_asrc[w];
    // self-loop logits
    float e0s = asf.x + ad.x; e0s = e0s > 0.f ? e0s : NEG * e0s;
    float e1s = asf.y + ad.y; e1s = e1s > 0.f ? e1s : NEG * e1s;

    float m0 = e0s, m1 = e1s;
    for (int j = lane; j < deg; j += 32) {
        float2 a = g_asrc[g_srt[start + j]];
        float e0 = a.x + ad.x; e0 = e0 > 0.f ? e0 : NEG * e0;
        float e1 = a.y + ad.y; e1 = e1 > 0.f ? e1 : NEG * e1;
        g_ex[start + j] = make_float2(e0, e1);
        m0 = fmaxf(m0, e0); m1 = fmaxf(m1, e1);
    }
    #pragma unroll
    for (int o = 16; o; o >>= 1) {
        m0 = fmaxf(m0, __shfl_xor_sync(0xFFFFFFFFu, m0, o));
        m1 = fmaxf(m1, __shfl_xor_sync(0xFFFFFFFFu, m1, o));
    }

    float s0 = 0.f, s1 = 0.f;
    for (int j = lane; j < deg; j += 32) {
        float2 e = g_ex[start + j];
        float x0 = __expf(e.x - m0);
        float x1 = __expf(e.y - m1);
        g_ex[start + j] = make_float2(x0, x1);
        s0 += x0; s1 += x1;
    }
    #pragma unroll
    for (int o = 16; o; o >>= 1) {
        s0 += __shfl_xor_sync(0xFFFFFFFFu, s0, o);
        s1 += __shfl_xor_sync(0xFFFFFFFFu, s1, o);
    }
    float xs0 = __expf(e0s - m0);
    float xs1 = __expf(e1s - m1);
    s0 += xs0; s1 += xs1;

    __syncwarp();   // pass-B stores visible across the warp

    int head = lane >> 4;
    float inv = 1.f / ((head ? s1 : s0) + 1e-16f);
    const float4* H4 = (const float4*)g_h;
    float4 acc = make_float4(0.f, 0.f, 0.f, 0.f);
    for (int j = 0; j < deg; j++) {
        int srcj = g_srt[start + j];
        float2 e = g_ex[start + j];
        float alpha = (head ? e.y : e.x) * inv;
        float4 hv = H4[srcj * 32 + lane];
        acc.x += alpha * hv.x;
        acc.y += alpha * hv.y;
        acc.z += alpha * hv.z;
        acc.w += alpha * hv.w;
    }
    {   // self-loop
        float alpha = (head ? xs1 : xs0) * inv;
        float4 hv = H4[w * 32 + lane];
        acc.x += alpha * hv.x;
        acc.y += alpha * hv.y;
        acc.z += alpha * hv.z;
        acc.w += alpha * hv.w;
    }
    float4 b = ((const float4*)bias)[lane];
    acc.x += b.x; acc.y += b.y; acc.z += b.z; acc.w += b.w;
    ((float4*)g_agg)[w * 32 + lane] = acc;
}

// ---------------- batch norm (reads g_agg) ----------------
__global__ void k_zero_stats() {
    int t = threadIdx.x;
    if (t < FD) { g_bnsum[t] = 0.0; g_bnsq[t] = 0.0; }
}

__global__ void k_bnstats() {
    int c = threadIdx.x & 127;
    int g = threadIdx.x >> 7;            // 0/1 row group
    double sum = 0.0, sq = 0.0;
    for (int r = blockIdx.x * 2 + g; r < NN; r += gridDim.x * 2) {
        float v = g_agg[r * FD + c];
        sum += (double)v;
        sq  += (double)v * (double)v;
    }
    atomicAdd(&g_bnsum[c], sum);
    atomicAdd(&g_bnsq[c],  sq);
}

__global__ void k_bnapply(const float* __restrict__ gamma,
                          const float* __restrict__ beta,
                          float* __restrict__ out, int to_out) {
    int i = blockIdx.x * blockDim.x + threadIdx.x;   // float4 index
    if (i >= NN * 32) return;
    int c4 = (i & 31) * 4;
    float4 v  = ((const float4*)g_agg)[i];
    float4 gm = ((const float4*)gamma)[i & 31];
    float4 bt = ((const float4*)beta)[i & 31];
    float res[4];
    float vin[4] = {v.x, v.y, v.z, v.w};
    float gs[4]  = {gm.x, gm.y, gm.z, gm.w};
    float bs[4]  = {bt.x, bt.y, bt.z, bt.w};
    #pragma unroll
    for (int k = 0; k < 4; k++) {
        int c = c4 + k;
        float mean = (float)(g_bnsum[c] / (double)NN);
        float var  = (float)(g_bnsq[c] / (double)NN) - mean * mean;
        float is   = rsqrtf(var + BN_EPS);
        float y = (vin[k] - mean) * is * gs[k] + bs[k];
        res[k] = y > 0.f ? y : expm1f(y);
    }
    float4* dst = to_out ? (float4*)out : (float4*)g_x2;
    dst[i] = make_float4(res[0], res[1], res[2], res[3]);
}

// ---------------- launch: kernel launches ONLY (graph-capture safe) ----------------
extern "C" void kernel_launch(void* const* d_in, const int* in_sizes, int n_in,
                              void* d_out, int out_size) {
    const float* x        = (const float*)d_in[0];
    const int*   eidx     = (const int*)d_in[1];     // int32 (JAX x64 disabled)
    const float* W1       = (const float*)d_in[2];
    const float* att_src1 = (const float*)d_in[3];
    const float* att_dst1 = (const float*)d_in[4];
    const float* b1       = (const float*)d_in[5];
    const float* W2       = (const float*)d_in[6];
    const float* att_src2 = (const float*)d_in[7];
    const float* att_dst2 = (const float*)d_in[8];
    const float* b2       = (const float*)d_in[9];
    const float* g1       = (const float*)d_in[10];
    const float* be1      = (const float*)d_in[11];
    const float* g2       = (const float*)d_in[12];
    const float* be2      = (const float*)d_in[13];
    float* out = (float*)d_out;

    const int* esrc = eidx;
    const int* edst = eidx + EE;

    const int WARP_BLOCKS = NN / 8;          // 6250 blocks x 8 warps = 50000 warps
    const int GEMM_BLOCKS = (NN + 31) / 32;  // 1563
    const int E_BLOCKS    = (EE + 255) / 256;

    // --- build CSR by destination (shared by both layers) ---
    k_zero_counts<<<(NN + 255) / 256, 256>>>();
    k_hist<<<E_BLOCKS, 256>>>(edst);
    k_scan<<<1, 1024>>>();
    k_scatter<<<E_BLOCKS, 256>>>(esrc, edst);

    // --- layer 1 ---
    k_gemm<<<GEMM_BLOCKS, 256>>>(x, W1, 0);
    k_att<<<WARP_BLOCKS, 256>>>(att_src1, att_dst1);
    k_agg<<<WARP_BLOCKS, 256>>>(b1);
    k_zero_stats<<<1, 256>>>();
    k_bnstats<<<256, 256>>>();
    k_bnapply<<<WARP_BLOCKS, 256>>>(g1, be1, out, 0);

    // --- layer 2 ---
    k_gemm<<<GEMM_BLOCKS, 256>>>(x, W2, 1);
    k_att<<<WARP_BLOCKS, 256>>>(att_src2, att_dst2);
    k_agg<<<WARP_BLOCKS, 256>>>(b2);
    k_zero_stats<<<1, 256>>>();
    k_bnstats<<<256, 256>>>();
    k_bnapply<<<WARP_BLOCKS, 256>>>(g2, be2, out, 1);
}

// round 6
// speedup vs baseline: 1.0907x; 1.0907x over previous
#include <cuda_runtime.h>
#include <cuda_bf16.h>

#define NN 50000
#define EE 800000
#define FD 128           // hidden = heads*C = 2*64
#define NEG 0.2f
#define BN_EPS 1e-5f

// ---------------- scratch (device globals; referenced ONLY inside kernels) ----
__device__ __align__(16) float  g_h[NN * FD];    // per-layer features (GEMM out)
__device__ __align__(16) float  g_agg[NN * FD];  // GAT aggregate output (pre-BN)
__device__ float2 g_asrc[NN];          // per-node attention src scores (2 heads)
__device__ float2 g_adst[NN];          // per-node attention dst scores (2 heads)
__device__ int    g_counts[NN];
__device__ int    g_cursor[NN];
__device__ int    g_offsets[NN + 1];
__device__ int    g_srt[EE];           // src node ids, sorted by dst (CSR)
__device__ double g_bnsum[2][FD];
__device__ double g_bnsq[2][FD];

__device__ __forceinline__ int clampN(int v) {
    return v < 0 ? 0 : (v >= NN ? NN - 1 : v);
}
__device__ __forceinline__ float lrelu(float v) { return v > 0.f ? v : NEG * v; }

// ---------------- init: zero counts + both BN stat slots ----------------
__global__ void k_zero() {
    int i = blockIdx.x * blockDim.x + threadIdx.x;
    if (i < NN) g_counts[i] = 0;
    if (blockIdx.x == 0 && threadIdx.x < FD) {
        g_bnsum[0][threadIdx.x] = 0.0; g_bnsq[0][threadIdx.x] = 0.0;
        g_bnsum[1][threadIdx.x] = 0.0; g_bnsq[1][threadIdx.x] = 0.0;
    }
}

// ---------------- counting sort by destination (int4 vectorized) ----------------
__global__ void k_hist(const int* __restrict__ dst) {
    int e4 = blockIdx.x * blockDim.x + threadIdx.x;
    if (e4 < EE / 4) {
        int4 d = ((const int4*)dst)[e4];
        atomicAdd(&g_counts[clampN(d.x)], 1);
        atomicAdd(&g_counts[clampN(d.y)], 1);
        atomicAdd(&g_counts[clampN(d.z)], 1);
        atomicAdd(&g_counts[clampN(d.w)], 1);
    }
}

__global__ void k_scan() {
    __shared__ int ssum[1024];
    const int CH = (NN + 1023) / 1024;   // 49
    int t = threadIdx.x;
    int base = t * CH;
    int s = 0;
    for (int i = 0; i < CH; i++) {
        int idx = base + i;
        if (idx < NN) s += g_counts[idx];
    }
    ssum[t] = s;
    __syncthreads();
    for (int o = 1; o < 1024; o <<= 1) {
        int u = (t >= o) ? ssum[t - o] : 0;
        __syncthreads();
        ssum[t] += u;
        __syncthreads();
    }
    int off = ssum[t] - s;
    for (int i = 0; i < CH; i++) {
        int idx = base + i;
        if (idx < NN) {
            g_offsets[idx] = off;
            g_cursor[idx]  = off;
            off += g_counts[idx];
        }
    }
    if (t == 0) g_offsets[NN] = EE;
}

__global__ void k_scatter(const int* __restrict__ src,
                          const int* __restrict__ dst) {
    int e4 = blockIdx.x * blockDim.x + threadIdx.x;
    if (e4 < EE / 4) {
        int4 d = ((const int4*)dst)[e4];
        int4 s = ((const int4*)src)[e4];
        int p;
        p = atomicAdd(&g_cursor[clampN(d.x)], 1); if (p >= 0 && p < EE) g_srt[p] = clampN(s.x);
        p = atomicAdd(&g_cursor[clampN(d.y)], 1); if (p >= 0 && p < EE) g_srt[p] = clampN(s.y);
        p = atomicAdd(&g_cursor[clampN(d.z)], 1); if (p >= 0 && p < EE) g_srt[p] = clampN(s.z);
        p = atomicAdd(&g_cursor[clampN(d.w)], 1); if (p >= 0 && p < EE) g_srt[p] = clampN(s.w);
    }
}

// ---------------- GEMM + attention-score epilogue (+ fused BN/ELU input for L2) ---
// mode 0: read X raw. mode 1: read g_agg with BN(slot0)+ELU applied on the fly.
// Epilogue computes a_src/a_dst per row from register accumulators.
__global__ void k_gemm(const float* __restrict__ X, const float* __restrict__ W,
                       const float* __restrict__ gamma, const float* __restrict__ beta,
                       const float* __restrict__ att_s, const float* __restrict__ att_d,
                       int mode) {
    __shared__ float Ws[32 * FD];   // 16 KB (K-chunk of W)
    __shared__ float Xs[32 * FD];   // 16 KB (32-row X tile)
    __shared__ float sA[FD], sB[FD];
    int t = threadIdx.x;
    int rb = blockIdx.x * 32;

    if (mode) {
        if (t < FD) {
            double mean = g_bnsum[0][t] / (double)NN;
            double var  = g_bnsq[0][t] / (double)NN - mean * mean;
            float a = gamma[t] * rsqrtf((float)var + BN_EPS);
            sA[t] = a;
            sB[t] = beta[t] - (float)mean * a;
        }
        __syncthreads();
    }

    // load X tile (1024 float4), applying BN+ELU for mode 1
    const float4* X4 = (const float4*)(mode ? (const float*)g_agg : X);
    float4* Xs4 = (float4*)Xs;
    for (int i = t; i < 32 * 32; i += 256) {
        int r = i >> 5, c = i & 31;
        int gr = rb + r;
        float4 v = (gr < NN) ? X4[gr * 32 + c] : make_float4(0.f, 0.f, 0.f, 0.f);
        if (mode) {
            int cc = c * 4;
            float y;
            y = sA[cc + 0] * v.x + sB[cc + 0]; v.x = y > 0.f ? y : expm1f(y);
            y = sA[cc + 1] * v.y + sB[cc + 1]; v.y = y > 0.f ? y : expm1f(y);
            y = sA[cc + 2] * v.z + sB[cc + 2]; v.z = y > 0.f ? y : expm1f(y);
            y = sA[cc + 3] * v.w + sB[cc + 3]; v.w = y > 0.f ? y : expm1f(y);
        }
        Xs4[i] = v;
    }

    int lane = t & 31;
    int warp = t >> 5;           // 8 warps: rows warp, warp+8, +16, +24
    float4 acc[4] = {{0,0,0,0},{0,0,0,0},{0,0,0,0},{0,0,0,0}};
    float4* Ws4 = (float4*)Ws;

    #pragma unroll
    for (int chunk = 0; chunk < 4; chunk++) {
        __syncthreads();   // X tile ready / previous chunk consumed
        const float4* W4 = (const float4*)(W + chunk * 32 * FD);
        for (int i = t; i < 32 * 32; i += 256) Ws4[i] = W4[i];
        __syncthreads();

        #pragma unroll 4
        for (int k = 0; k < 32; k++) {
            float4 wv = *(const float4*)&Ws[k * FD + lane * 4];
            #pragma unroll
            for (int i = 0; i < 4; i++) {
                float xv = Xs[(warp + i * 8) * FD + chunk * 32 + k];
                acc[i].x += xv * wv.x;
                acc[i].y += xv * wv.y;
                acc[i].z += xv * wv.z;
                acc[i].w += xv * wv.w;
            }
        }
    }

    // epilogue: store h rows + attention scores
    float4 as4 = ((const float4*)att_s)[lane];  // [2,64] flat matches channel order
    float4 ad4 = ((const float4*)att_d)[lane];
    #pragma unroll
    for (int i = 0; i < 4; i++) {
        int r = rb + warp + i * 8;
        float ds = acc[i].x * as4.x + acc[i].y * as4.y + acc[i].z * as4.z + acc[i].w * as4.w;
        float dd = acc[i].x * ad4.x + acc[i].y * ad4.y + acc[i].z * ad4.z + acc[i].w * ad4.w;
        #pragma unroll
        for (int o = 8; o; o >>= 1) {   // reduce within 16-lane head groups
            ds += __shfl_xor_sync(0xFFFFFFFFu, ds, o);
            dd += __shfl_xor_sync(0xFFFFFFFFu, dd, o);
        }
        if (r < NN) {
            ((float4*)g_h)[r * 32 + lane] = acc[i];
            if (lane == 0)  { g_asrc[r].x = ds; g_adst[r].x = dd; }
            if (lane == 16) { g_asrc[r].y = ds; g_adst[r].y = dd; }
        }
    }
}

// ---------------- warp-per-dst aggregation: register/smem softmax, no g_ex -------
__global__ void k_agg(const float* __restrict__ bias) {
    __shared__ int   s_src[8][32];
    __shared__ float s_a0[8][32];
    __shared__ float s_a1[8][32];
    int wb   = threadIdx.x >> 5;
    int lane = threadIdx.x & 31;
    int w = (blockIdx.x * blockDim.x + threadIdx.x) >> 5;
    if (w >= NN) return;
    int start = g_offsets[w];
    int deg   = g_offsets[w + 1] - start;

    float2 ad    = g_adst[w];
    float2 aself = g_asrc[w];

    // lane-private edge (first 32 edges)
    bool have = lane < deg;
    int mysrc = 0;
    float2 ma = make_float2(-1e30f, -1e30f);
    if (have) { mysrc = g_srt[start + lane]; ma = g_asrc[mysrc]; }

    // pass A: max of asrc over neighborhood (+self). leaky & +adst are monotone,
    // so max(leaky(a+ad)) == leaky(max(a)+ad).
    float M0 = fmaxf(ma.x, aself.x);
    float M1 = fmaxf(ma.y, aself.y);
    for (int j = 32 + lane; j < deg; j += 32) {
        float2 a = g_asrc[g_srt[start + j]];
        M0 = fmaxf(M0, a.x); M1 = fmaxf(M1, a.y);
    }
    #pragma unroll
    for (int o = 16; o; o >>= 1) {
        M0 = fmaxf(M0, __shfl_xor_sync(0xFFFFFFFFu, M0, o));
        M1 = fmaxf(M1, __shfl_xor_sync(0xFFFFFFFFu, M1, o));
    }
    float m0 = lrelu(M0 + ad.x);
    float m1 = lrelu(M1 + ad.y);

    // pass B: exp + sum
    float ex0 = 0.f, ex1 = 0.f;
    if (have) {
        ex0 = __expf(lrelu(ma.x + ad.x) - m0);
        ex1 = __expf(lrelu(ma.y + ad.y) - m1);
    }
    float s0 = ex0, s1 = ex1;
    for (int j = 32 + lane; j < deg; j += 32) {
        float2 a = g_asrc[g_srt[start + j]];
        s0 += __expf(lrelu(a.x + ad.x) - m0);
        s1 += __expf(lrelu(a.y + ad.y) - m1);
    }
    #pragma unroll
    for (int o = 16; o; o >>= 1) {
        s0 += __shfl_xor_sync(0xFFFFFFFFu, s0, o);
        s1 += __shfl_xor_sync(0xFFFFFFFFu, s1, o);
    }
    float xs0 = __expf(lrelu(aself.x + ad.x) - m0);
    float xs1 = __expf(lrelu(aself.y + ad.y) - m1);
    s0 += xs0; s1 += xs1;
    float inv0 = 1.f / (s0 + 1e-16f);
    float inv1 = 1.f / (s1 + 1e-16f);

    // stage per-lane edges for pass C
    s_src[wb][lane] = mysrc;
    s_a0[wb][lane]  = ex0 * inv0;
    s_a1[wb][lane]  = ex1 * inv1;
    __syncwarp();

    int head = lane >> 4;
    const float4* H4 = (const float4*)g_h;

    // self-loop first
    float salpha = head ? xs1 * inv1 : xs0 * inv0;
    float4 hv = H4[w * 32 + lane];
    float4 acc = make_float4(salpha * hv.x, salpha * hv.y, salpha * hv.z, salpha * hv.w);

    const float* sal = head ? s_a1[wb] : s_a0[wb];
    int nd = deg < 32 ? deg : 32;
    #pragma unroll 4
    for (int j = 0; j < nd; j++) {
        int srcj = s_src[wb][j];
        float alpha = sal[j];
        float4 v = H4[srcj * 32 + lane];
        acc.x += alpha * v.x;
        acc.y += alpha * v.y;
        acc.z += alpha * v.z;
        acc.w += alpha * v.w;
    }
    // rare tail (deg > 32): recompute alpha inline
    for (int j = 32; j < deg; j++) {
        int srcj = g_srt[start + j];
        float2 a = g_asrc[srcj];
        float e = head ? (lrelu(a.y + ad.y) - m1) : (lrelu(a.x + ad.x) - m0);
        float alpha = __expf(e) * (head ? inv1 : inv0);
        float4 v = H4[srcj * 32 + lane];
        acc.x += alpha * v.x;
        acc.y += alpha * v.y;
        acc.z += alpha * v.z;
        acc.w += alpha * v.w;
    }

    float4 b = ((const float4*)bias)[lane];
    acc.x += b.x; acc.y += b.y; acc.z += b.z; acc.w += b.w;
    ((float4*)g_agg)[w * 32 + lane] = acc;
}

// ---------------- batch norm stats: fp32 per-thread partials, fp64 combine -------
__global__ void k_bnstats(int slot) {
    int c = threadIdx.x & 127;
    int g = threadIdx.x >> 7;            // 0/1 row group
    float sum = 0.f, sq = 0.f;
    for (int r = blockIdx.x * 2 + g; r < NN; r += gridDim.x * 2) {
        float v = g_agg[r * FD + c];
        sum += v;
        sq = fmaf(v, v, sq);
    }
    atomicAdd(&g_bnsum[slot][c], (double)sum);
    atomicAdd(&g_bnsq[slot][c],  (double)sq);
}

// ---------------- final BN+ELU (layer 2 only) -> out ----------------
__global__ void k_bnapply(const float* __restrict__ gamma,
                          const float* __restrict__ beta,
                          float* __restrict__ out) {
    int i = blockIdx.x * blockDim.x + threadIdx.x;   // float4 index
    if (i >= NN * 32) return;
    int c4 = (i & 31) * 4;
    float4 v  = ((const float4*)g_agg)[i];
    float4 gm = ((const float4*)gamma)[i & 31];
    float4 bt = ((const float4*)beta)[i & 31];
    float res[4];
    float vin[4] = {v.x, v.y, v.z, v.w};
    float gs[4]  = {gm.x, gm.y, gm.z, gm.w};
    float bs[4]  = {bt.x, bt.y, bt.z, bt.w};
    #pragma unroll
    for (int k = 0; k < 4; k++) {
        int c = c4 + k;
        float mean = (float)(g_bnsum[1][c] / (double)NN);
        float var  = (float)(g_bnsq[1][c] / (double)NN) - mean * mean;
        float is   = rsqrtf(var + BN_EPS);
        float y = (vin[k] - mean) * is * gs[k] + bs[k];
        res[k] = y > 0.f ? y : expm1f(y);
    }
    ((float4*)out)[i] = make_float4(res[0], res[1], res[2], res[3]);
}

// ---------------- launch: kernel launches ONLY (graph-capture safe) ----------------
extern "C" void kernel_launch(void* const* d_in, const int* in_sizes, int n_in,
                              void* d_out, int out_size) {
    const float* x        = (const float*)d_in[0];
    const int*   eidx     = (const int*)d_in[1];     // int32 (JAX x64 disabled)
    const float* W1       = (const float*)d_in[2];
    const float* att_src1 = (const float*)d_in[3];
    const float* att_dst1 = (const float*)d_in[4];
    const float* b1       = (const float*)d_in[5];
    const float* W2       = (const float*)d_in[6];
    const float* att_src2 = (const float*)d_in[7];
    const float* att_dst2 = (const float*)d_in[8];
    const float* b2       = (const float*)d_in[9];
    const float* g1       = (const float*)d_in[10];
    const float* be1      = (const float*)d_in[11];
    const float* g2       = (const float*)d_in[12];
    const float* be2      = (const float*)d_in[13];
    float* out = (float*)d_out;

    const int* esrc = eidx;
    const int* edst = eidx + EE;

    const int WARP_BLOCKS = NN / 8;              // 6250
    const int GEMM_BLOCKS = (NN + 31) / 32;      // 1563
    const int E4_BLOCKS   = (EE / 4 + 255) / 256;

    // --- build CSR by destination (shared by both layers) ---
    k_zero<<<(NN + 255) / 256, 256>>>();
    k_hist<<<E4_BLOCKS, 256>>>(edst);
    k_scan<<<1, 1024>>>();
    k_scatter<<<E4_BLOCKS, 256>>>(esrc, edst);

    // --- layer 1 ---
    k_gemm<<<GEMM_BLOCKS, 256>>>(x, W1, g1, be1, att_src1, att_dst1, 0);
    k_agg<<<WARP_BLOCKS, 256>>>(b1);
    k_bnstats<<<256, 256>>>(0);

    // --- layer 2 (BN+ELU of layer 1 fused into GEMM input path) ---
    k_gemm<<<GEMM_BLOCKS, 256>>>(x, W2, g1, be1, att_src2, att_dst2, 1);
    k_agg<<<WARP_BLOCKS, 256>>>(b2);
    k_bnstats<<<256, 256>>>(1);
    k_bnapply<<<WARP_BLOCKS, 256>>>(g2, be2, out);
}